// round 2
// baseline (speedup 1.0000x reference)
#include <cuda_runtime.h>
#include <cuda_fp16.h>
#include <cstdint>

#define B_ 4
#define S_ 4096
#define E_ 512

// ---------------- GEMM tiling ----------------
#define BM 128
#define BN 128
#define BK 32
#define NTHREADS 256
#define LDS 40                    // smem row stride in halfs (pad 32->40: conflict-free ldmatrix)
#define ARR (BM * LDS)            // halfs per operand tile (5120)
#define STAGE_HALFS (4 * ARR)     // Ah, Al, Bh, Bl
#define SMEM_BYTES (2 * STAGE_HALFS * (int)sizeof(__half))  // 81920

// ---------------- device-global scratch (allocation-free rule) ----------------
__device__ __half g_xqh[(size_t)B_ * S_ * E_], g_xql[(size_t)B_ * S_ * E_];
__device__ __half g_xkh[(size_t)B_ * S_ * E_], g_xkl[(size_t)B_ * S_ * E_];
__device__ __half g_xvh[(size_t)B_ * S_ * E_], g_xvl[(size_t)B_ * S_ * E_];
__device__ __half g_wqh[E_ * E_], g_wql[E_ * E_];
__device__ __half g_wkh[E_ * E_], g_wkl[E_ * E_];
__device__ __half g_wvh[E_ * E_], g_wvl[E_ * E_];
__device__ __half g_qh[(size_t)B_ * S_ * E_], g_ql[(size_t)B_ * S_ * E_];
__device__ __half g_kh[(size_t)B_ * S_ * E_], g_kl[(size_t)B_ * S_ * E_];
__device__ __half g_vth[(size_t)B_ * E_ * S_], g_vtl[(size_t)B_ * E_ * S_];  // V transposed [B][E][S]
__device__ float  g_sc[(size_t)B_ * S_ * S_];                                 // scores fp32
__device__ __half g_ph[(size_t)B_ * S_ * S_], g_pl[(size_t)B_ * S_ * S_];     // softmax probs hi/lo

// ---------------- PTX helpers ----------------
__device__ __forceinline__ void cpasync16(const __half* smem_ptr, const __half* gptr) {
    uint32_t s = (uint32_t)__cvta_generic_to_shared((void*)smem_ptr);
    asm volatile("cp.async.cg.shared.global [%0], [%1], 16;\n" :: "r"(s), "l"(gptr));
}

__device__ __forceinline__ void ldm4(uint32_t* d, const __half* p) {
    uint32_t s = (uint32_t)__cvta_generic_to_shared((void*)p);
    asm volatile("ldmatrix.sync.aligned.m8n8.x4.shared.b16 {%0,%1,%2,%3}, [%4];"
                 : "=r"(d[0]), "=r"(d[1]), "=r"(d[2]), "=r"(d[3]) : "r"(s));
}

__device__ __forceinline__ void mma16816(float* c, const uint32_t* a, const uint32_t* b) {
    asm volatile("mma.sync.aligned.m16n8k16.row.col.f32.f16.f16.f32 "
                 "{%0,%1,%2,%3},{%4,%5,%6,%7},{%8,%9},{%0,%1,%2,%3};"
                 : "+f"(c[0]), "+f"(c[1]), "+f"(c[2]), "+f"(c[3])
                 : "r"(a[0]), "r"(a[1]), "r"(a[2]), "r"(a[3]), "r"(b[0]), "r"(b[1]));
}

__device__ __forceinline__ void store_split(__half* hi, __half* lo, size_t idx, float v) {
    __half h = __float2half_rn(v);
    hi[idx] = h;
    lo[idx] = __float2half_rn(v - __half2float(h));
}

// ---------------- split fp32 -> fp16 hi/lo ----------------
__global__ void split_kernel(const float* __restrict__ x, __half* __restrict__ hi,
                             __half* __restrict__ lo, int n) {
    int i = blockIdx.x * blockDim.x + threadIdx.x;
    if (i < n) {
        float v = x[i];
        __half h = __float2half_rn(v);
        hi[i] = h;
        lo[i] = __float2half_rn(v - __half2float(h));
    }
}

// ---------------- split-precision NT GEMM: C[M,N] = sum_k A[m,k] * B[n,k] ----------------
// A,B are fp16 hi/lo pairs, both K-major (ld = K). 3-term product: Ah*Bh + Ah*Bl + Al*Bh.
// mode 0: write fp32 C (ldc = N) to Cf (+ z*sCz)
// mode 1: write (acc + bias[n]) as fp16 hi/lo at [m*N + n]
// mode 2: write (acc + bias[n]) as fp16 hi/lo TRANSPOSED per-batch: [b][n][s], b=m>>12, s=m&4095
__device__ __forceinline__ void issue_tile(const __half* Ah, const __half* Al,
                                           const __half* Bh, const __half* Bl,
                                           int K, int m0, int n0, int k0,
                                           __half* sb, int t) {
#pragma unroll
    for (int i = 0; i < 2; i++) {
        int id = t + i * NTHREADS;          // 0..511
        int r = id >> 2;
        int cc = (id & 3) * 8;
        size_t ga = (size_t)(m0 + r) * K + k0 + cc;
        size_t gb = (size_t)(n0 + r) * K + k0 + cc;
        int so = r * LDS + cc;
        cpasync16(sb + so, Ah + ga);
        cpasync16(sb + ARR + so, Al + ga);
        cpasync16(sb + 2 * ARR + so, Bh + gb);
        cpasync16(sb + 3 * ARR + so, Bl + gb);
    }
    asm volatile("cp.async.commit_group;\n" ::: "memory");
}

__global__ void __launch_bounds__(NTHREADS)
gemm_split_kernel(const __half* __restrict__ Ah, const __half* __restrict__ Al, long long sAz,
                  const __half* __restrict__ Bh, const __half* __restrict__ Bl, long long sBz,
                  int M, int N, int K,
                  float* __restrict__ Cf, long long sCz,
                  __half* __restrict__ Chi, __half* __restrict__ Clo,
                  const float* __restrict__ bias, int mode) {
    extern __shared__ __half smp[];
    int z = blockIdx.z;
    Ah += (size_t)z * sAz;  Al += (size_t)z * sAz;
    Bh += (size_t)z * sBz;  Bl += (size_t)z * sBz;

    int m0 = blockIdx.y * BM, n0 = blockIdx.x * BN;
    int t = threadIdx.x;
    int lane = t & 31, w = t >> 5;
    int wm = w & 1, wn = w >> 1;            // 2 warps along M (64 each), 4 along N (32 each)
    int quad = lane >> 3, l8 = lane & 7;

    int a_row = wm * 64 + (quad & 1) * 8 + l8;   // + mi*16
    int a_col = (quad >> 1) * 8;                  // + ks
    int b_row = wn * 32 + (quad >> 1) * 8 + l8;   // + p*16
    int b_col = (quad & 1) * 8;                   // + ks

    float acc[4][4][4];
#pragma unroll
    for (int i = 0; i < 4; i++)
#pragma unroll
        for (int j = 0; j < 4; j++)
#pragma unroll
            for (int r = 0; r < 4; r++) acc[i][j][r] = 0.f;

    int KT = K / BK;
    issue_tile(Ah, Al, Bh, Bl, K, m0, n0, 0, smp, t);

    for (int kt = 0; kt < KT; kt++) {
        if (kt + 1 < KT) {
            issue_tile(Ah, Al, Bh, Bl, K, m0, n0, (kt + 1) * BK,
                       smp + ((kt + 1) & 1) * STAGE_HALFS, t);
            asm volatile("cp.async.wait_group 1;\n" ::: "memory");
        } else {
            asm volatile("cp.async.wait_group 0;\n" ::: "memory");
        }
        __syncthreads();

        const __half* st = smp + (kt & 1) * STAGE_HALFS;
#pragma unroll
        for (int combo = 0; combo < 3; combo++) {
            const __half* pA = st + (combo == 2 ? ARR : 0);
            const __half* pB = st + 2 * ARR + (combo == 1 ? ARR : 0);
#pragma unroll
            for (int ks = 0; ks < BK; ks += 16) {
                uint32_t a[4][4];
#pragma unroll
                for (int mi = 0; mi < 4; mi++)
                    ldm4(a[mi], pA + (a_row + mi * 16) * LDS + a_col + ks);
                uint32_t b[2][4];
#pragma unroll
                for (int p = 0; p < 2; p++)
                    ldm4(b[p], pB + (b_row + p * 16) * LDS + b_col + ks);
#pragma unroll
                for (int mi = 0; mi < 4; mi++)
#pragma unroll
                    for (int nj = 0; nj < 4; nj++)
                        mma16816(acc[mi][nj], a[mi], &b[nj >> 1][(nj & 1) * 2]);
            }
        }
        __syncthreads();
    }

    // -------- epilogue --------
    int row0 = m0 + wm * 64 + (lane >> 2);
    int col0 = n0 + wn * 32 + (lane & 3) * 2;

    if (mode == 0) {
        float* C = Cf + (size_t)z * sCz;
#pragma unroll
        for (int mi = 0; mi < 4; mi++) {
#pragma unroll
            for (int nj = 0; nj < 4; nj++) {
                int r = row0 + mi * 16, c = col0 + nj * 8;
                float2 v0 = make_float2(acc[mi][nj][0], acc[mi][nj][1]);
                float2 v1 = make_float2(acc[mi][nj][2], acc[mi][nj][3]);
                *reinterpret_cast<float2*>(C + (size_t)r * N + c) = v0;
                *reinterpret_cast<float2*>(C + (size_t)(r + 8) * N + c) = v1;
            }
        }
    } else if (mode == 1) {
#pragma unroll
        for (int mi = 0; mi < 4; mi++) {
#pragma unroll
            for (int nj = 0; nj < 4; nj++) {
                int r = row0 + mi * 16, c = col0 + nj * 8;
                float b0 = bias[c], b1 = bias[c + 1];
                store_split(Chi, Clo, (size_t)r * N + c,           acc[mi][nj][0] + b0);
                store_split(Chi, Clo, (size_t)r * N + c + 1,       acc[mi][nj][1] + b1);
                store_split(Chi, Clo, (size_t)(r + 8) * N + c,     acc[mi][nj][2] + b0);
                store_split(Chi, Clo, (size_t)(r + 8) * N + c + 1, acc[mi][nj][3] + b1);
            }
        }
    } else {  // mode 2: transposed per-batch [b][n][s]
#pragma unroll
        for (int mi = 0; mi < 4; mi++) {
#pragma unroll
            for (int nj = 0; nj < 4; nj++) {
                int r = row0 + mi * 16, c = col0 + nj * 8;
                float b0 = bias[c], b1 = bias[c + 1];
#pragma unroll
                for (int rr = 0; rr < 2; rr++) {
                    int tok = r + rr * 8;
                    int bb = tok >> 12, s = tok & (S_ - 1);
                    size_t base = ((size_t)bb * E_) * S_ + s;
                    store_split(Chi, Clo, base + (size_t)c * S_,       acc[mi][nj][rr * 2 + 0] + b0);
                    store_split(Chi, Clo, base + (size_t)(c + 1) * S_, acc[mi][nj][rr * 2 + 1] + b1);
                }
            }
        }
    }
}

// ---------------- row softmax: scores fp32 -> P hi/lo fp16 ----------------
__device__ __forceinline__ float warpMax(float v) {
#pragma unroll
    for (int o = 16; o; o >>= 1) v = fmaxf(v, __shfl_xor_sync(0xffffffffu, v, o));
    return v;
}
__device__ __forceinline__ float warpSum(float v) {
#pragma unroll
    for (int o = 16; o; o >>= 1) v += __shfl_xor_sync(0xffffffffu, v, o);
    return v;
}

__global__ void __launch_bounds__(256) softmax_kernel(const float* __restrict__ Sc,
                                                      __half* __restrict__ Ph,
                                                      __half* __restrict__ Pl) {
    __shared__ float red[8];
    __shared__ float bcast;
    int row = blockIdx.x;
    int t = threadIdx.x;
    int lane = t & 31, w = t >> 5;
    const float* sr = Sc + (size_t)row * S_;

    float v[16];
#pragma unroll
    for (int i = 0; i < 16; i++) v[i] = sr[i * 256 + t];

    float m = v[0];
#pragma unroll
    for (int i = 1; i < 16; i++) m = fmaxf(m, v[i]);
    m = warpMax(m);
    if (lane == 0) red[w] = m;
    __syncthreads();
    if (t == 0) {
        float x = red[0];
#pragma unroll
        for (int j = 1; j < 8; j++) x = fmaxf(x, red[j]);
        bcast = x;
    }
    __syncthreads();
    m = bcast;

    float e[16];
    float s = 0.f;
#pragma unroll
    for (int i = 0; i < 16; i++) { e[i] = __expf(v[i] - m); s += e[i]; }
    s = warpSum(s);
    __syncthreads();
    if (lane == 0) red[w] = s;
    __syncthreads();
    if (t == 0) {
        float x = 0.f;
#pragma unroll
        for (int j = 0; j < 8; j++) x += red[j];
        bcast = x;
    }
    __syncthreads();
    float inv = 1.0f / bcast;

    size_t base = (size_t)row * S_ + t;
#pragma unroll
    for (int i = 0; i < 16; i++) {
        float p = e[i] * inv;
        __half h = __float2half_rn(p);
        Ph[base + (size_t)i * 256] = h;
        Pl[base + (size_t)i * 256] = __float2half_rn(p - __half2float(h));
    }
}

// ---------------- host ----------------
#define GETSYM(p, s) do { void* _t = nullptr; cudaGetSymbolAddress(&_t, s); p = (__half*)_t; } while (0)

extern "C" void kernel_launch(void* const* d_in, const int* in_sizes, int n_in,
                              void* d_out, int out_size) {
    const float* q_in = (const float*)d_in[0];
    const float* k_in = (const float*)d_in[1];
    const float* v_in = (const float*)d_in[2];
    const float* Wq   = (const float*)d_in[3];
    const float* bq   = (const float*)d_in[4];
    const float* Wk   = (const float*)d_in[5];
    const float* bk   = (const float*)d_in[6];
    const float* Wv   = (const float*)d_in[7];
    const float* bv   = (const float*)d_in[8];
    float* out = (float*)d_out;

    cudaFuncSetAttribute(gemm_split_kernel, cudaFuncAttributeMaxDynamicSharedMemorySize, SMEM_BYTES);

    __half *xqh, *xql, *xkh, *xkl, *xvh, *xvl;
    __half *wqh, *wql, *wkh, *wkl, *wvh, *wvl;
    __half *qh, *ql, *kh, *kl, *vth, *vtl, *ph, *pl;
    float* sc;
    GETSYM(xqh, g_xqh); GETSYM(xql, g_xql);
    GETSYM(xkh, g_xkh); GETSYM(xkl, g_xkl);
    GETSYM(xvh, g_xvh); GETSYM(xvl, g_xvl);
    GETSYM(wqh, g_wqh); GETSYM(wql, g_wql);
    GETSYM(wkh, g_wkh); GETSYM(wkl, g_wkl);
    GETSYM(wvh, g_wvh); GETSYM(wvl, g_wvl);
    GETSYM(qh, g_qh);   GETSYM(ql, g_ql);
    GETSYM(kh, g_kh);   GETSYM(kl, g_kl);
    GETSYM(vth, g_vth); GETSYM(vtl, g_vtl);
    GETSYM(ph, g_ph);   GETSYM(pl, g_pl);
    { void* _t = nullptr; cudaGetSymbolAddress(&_t, g_sc); sc = (float*)_t; }

    int nx = B_ * S_ * E_;
    split_kernel<<<(nx + 255) / 256, 256>>>(q_in, xqh, xql, nx);
    split_kernel<<<(nx + 255) / 256, 256>>>(k_in, xkh, xkl, nx);
    split_kernel<<<(nx + 255) / 256, 256>>>(v_in, xvh, xvl, nx);
    int nw = E_ * E_;
    split_kernel<<<(nw + 255) / 256, 256>>>(Wq, wqh, wql, nw);
    split_kernel<<<(nw + 255) / 256, 256>>>(Wk, wkh, wkl, nw);
    split_kernel<<<(nw + 255) / 256, 256>>>(Wv, wvh, wvl, nw);

    // QKV projections: C[16384,512] = X * W^T + b
    dim3 gp(E_ / BN, (B_ * S_) / BM, 1);
    gemm_split_kernel<<<gp, NTHREADS, SMEM_BYTES>>>(xqh, xql, 0, wqh, wql, 0,
        B_ * S_, E_, E_, nullptr, 0, qh, ql, bq, 1);
    gemm_split_kernel<<<gp, NTHREADS, SMEM_BYTES>>>(xkh, xkl, 0, wkh, wkl, 0,
        B_ * S_, E_, E_, nullptr, 0, kh, kl, bk, 1);
    gemm_split_kernel<<<gp, NTHREADS, SMEM_BYTES>>>(xvh, xvl, 0, wvh, wvl, 0,
        B_ * S_, E_, E_, nullptr, 0, vth, vtl, bv, 2);   // V written transposed [B][E][S]

    // scores[b] = Q[b] * K[b]^T   (4096x4096x512 per batch)
    dim3 gs(S_ / BN, S_ / BM, B_);
    gemm_split_kernel<<<gs, NTHREADS, SMEM_BYTES>>>(qh, ql, (long long)S_ * E_,
        kh, kl, (long long)S_ * E_, S_, S_, E_,
        sc, (long long)S_ * S_, nullptr, nullptr, nullptr, 0);

    // row softmax -> P hi/lo
    softmax_kernel<<<B_ * S_, 256>>>(sc, ph, pl);

    // O[b] = P[b] * V[b]  via  P (K-major) x vT (K-major)   (4096x512x4096 per batch)
    dim3 gv(E_ / BN, S_ / BM, B_);
    gemm_split_kernel<<<gv, NTHREADS, SMEM_BYTES>>>(ph, pl, (long long)S_ * S_,
        vth, vtl, (long long)E_ * S_, S_, E_, S_,
        out, (long long)S_ * E_, nullptr, nullptr, nullptr, 0);
}

// round 6
// speedup vs baseline: 1.2642x; 1.2642x over previous
#include <cuda_runtime.h>
#include <cuda_fp16.h>
#include <cstdint>

#define B_ 4
#define S_ 4096
#define E_ 512

// ---------------- GEMM tiling ----------------
#define BM 128
#define BN 128
#define BK 32
#define NTHREADS 256
#define LDS 40                    // smem row stride in halfs (pad 32->40: conflict-free ldmatrix)
#define ARR (BM * LDS)            // halfs per operand tile (5120)

// ---------------- device-global scratch (allocation-free rule) ----------------
__device__ __half g_xqh[(size_t)B_ * S_ * E_], g_xql[(size_t)B_ * S_ * E_];
__device__ __half g_xkh[(size_t)B_ * S_ * E_], g_xkl[(size_t)B_ * S_ * E_];
__device__ __half g_xvh[(size_t)B_ * S_ * E_], g_xvl[(size_t)B_ * S_ * E_];
__device__ __half g_wqh[E_ * E_], g_wql[E_ * E_];
__device__ __half g_wkh[E_ * E_], g_wkl[E_ * E_];
__device__ __half g_wvh[E_ * E_], g_wvl[E_ * E_];
__device__ __half g_qh[(size_t)B_ * S_ * E_], g_ql[(size_t)B_ * S_ * E_];
__device__ __half g_kh[(size_t)B_ * S_ * E_], g_kl[(size_t)B_ * S_ * E_];
__device__ __half g_vth[(size_t)B_ * E_ * S_], g_vtl[(size_t)B_ * E_ * S_];  // V^T hi/lo [B][E][S]
__device__ float  g_sc[(size_t)B_ * S_ * S_];                                 // scores fp32
__device__ __half g_ph[(size_t)B_ * S_ * S_];                                 // softmax probs hi

// ---------------- PTX helpers ----------------
__device__ __forceinline__ void cpasync16(const __half* smem_ptr, const __half* gptr) {
    uint32_t s = (uint32_t)__cvta_generic_to_shared((void*)smem_ptr);
    asm volatile("cp.async.cg.shared.global [%0], [%1], 16;\n" :: "r"(s), "l"(gptr));
}

__device__ __forceinline__ void ldm4(uint32_t* d, const __half* p) {
    uint32_t s = (uint32_t)__cvta_generic_to_shared((void*)p);
    asm volatile("ldmatrix.sync.aligned.m8n8.x4.shared.b16 {%0,%1,%2,%3}, [%4];"
                 : "=r"(d[0]), "=r"(d[1]), "=r"(d[2]), "=r"(d[3]) : "r"(s));
}

__device__ __forceinline__ void mma16816(float* c, const uint32_t* a, const uint32_t* b) {
    asm volatile("mma.sync.aligned.m16n8k16.row.col.f32.f16.f16.f32 "
                 "{%0,%1,%2,%3},{%4,%5,%6,%7},{%8,%9},{%0,%1,%2,%3};"
                 : "+f"(c[0]), "+f"(c[1]), "+f"(c[2]), "+f"(c[3])
                 : "r"(a[0]), "r"(a[1]), "r"(a[2]), "r"(a[3]), "r"(b[0]), "r"(b[1]));
}

__device__ __forceinline__ void store_split(__half* hi, __half* lo, size_t idx, float v) {
    __half h = __float2half_rn(v);
    hi[idx] = h;
    lo[idx] = __float2half_rn(v - __half2float(h));
}

// ---------------- split fp32 -> fp16 hi/lo (3 tensors per launch) ----------------
__global__ void split3_kernel(const float* __restrict__ a, const float* __restrict__ b,
                              const float* __restrict__ c,
                              __half* ah, __half* al, __half* bh, __half* bl,
                              __half* ch, __half* cl, int n) {
    int i = blockIdx.x * blockDim.x + threadIdx.x;
    if (i < n) {
        float v;
        __half h;
        v = a[i]; h = __float2half_rn(v); ah[i] = h; al[i] = __float2half_rn(v - __half2float(h));
        v = b[i]; h = __float2half_rn(v); bh[i] = h; bl[i] = __float2half_rn(v - __half2float(h));
        v = c[i]; h = __float2half_rn(v); ch[i] = h; cl[i] = __float2half_rn(v - __half2float(h));
    }
}

// ---------------- split-precision NT GEMM: C[M,N] = sum_k A[m,k] * B[n,k] ----------------
// K-major fp16 operands. Combos by template C:
//   C==3: Ah*Bh + Ah*Bl + Al*Bh   (full split precision)
//   C==2: Ah*Bh + Ah*Bl           (A hi only x full B)
// Stage layout: [Ah | Bh | Bl? | Al?] each ARR halfs.
// mode 0: fp32 C (+z*sCz). mode 1: (acc+bias[n]) -> hi/lo at [m*N+n].
// mode 2: (acc+bias[n]) -> hi/lo transposed per-batch [b][n][s] (b=m>>12, s=m&4095).
template <int C>
__global__ void __launch_bounds__(NTHREADS)
gemm_split_kernel(const __half* __restrict__ Ah, const __half* __restrict__ Al, long long sAz,
                  const __half* __restrict__ Bh, const __half* __restrict__ Bl, long long sBz,
                  int M, int N, int K,
                  float* __restrict__ Cf, long long sCz,
                  __half* __restrict__ Chi, __half* __restrict__ Clo,
                  const float* __restrict__ bias, int mode) {
    constexpr int NTILE = (C == 3) ? 4 : 3;
    constexpr int STAGE_HALFS = NTILE * ARR;
    extern __shared__ __half smp[];
    int z = blockIdx.z;
    Ah += (size_t)z * sAz;
    Bh += (size_t)z * sBz;
    if (C >= 2) Bl += (size_t)z * sBz;
    if (C >= 3) Al += (size_t)z * sAz;

    int m0 = blockIdx.y * BM, n0 = blockIdx.x * BN;
    int t = threadIdx.x;
    int lane = t & 31, w = t >> 5;
    int wm = w & 1, wn = w >> 1;            // 2 warps along M (64 each), 4 along N (32 each)
    int quad = lane >> 3, l8 = lane & 7;

    int a_row = wm * 64 + (quad & 1) * 8 + l8;    // + mi*16
    int a_col = (quad >> 1) * 8;                  // + ks
    int b_row = wn * 32 + (quad >> 1) * 8 + l8;   // + p*16
    int b_col = (quad & 1) * 8;                   // + ks

    float acc[4][4][4];
#pragma unroll
    for (int i = 0; i < 4; i++)
#pragma unroll
        for (int j = 0; j < 4; j++)
#pragma unroll
            for (int r = 0; r < 4; r++) acc[i][j][r] = 0.f;

    auto issue_tile = [&](int k0, __half* sb) {
#pragma unroll
        for (int i = 0; i < 2; i++) {
            int id = t + i * NTHREADS;          // 0..511
            int r = id >> 2;
            int cc = (id & 3) * 8;
            size_t ga = (size_t)(m0 + r) * K + k0 + cc;
            size_t gb = (size_t)(n0 + r) * K + k0 + cc;
            int so = r * LDS + cc;
            cpasync16(sb + so, Ah + ga);
            cpasync16(sb + ARR + so, Bh + gb);
            if (C >= 2) cpasync16(sb + 2 * ARR + so, Bl + gb);
            if (C >= 3) cpasync16(sb + 3 * ARR + so, Al + ga);
        }
        asm volatile("cp.async.commit_group;\n" ::: "memory");
    };

    int KT = K / BK;
    issue_tile(0, smp);

    for (int kt = 0; kt < KT; kt++) {
        if (kt + 1 < KT) {
            issue_tile((kt + 1) * BK, smp + ((kt + 1) & 1) * STAGE_HALFS);
            asm volatile("cp.async.wait_group 1;\n" ::: "memory");
        } else {
            asm volatile("cp.async.wait_group 0;\n" ::: "memory");
        }
        __syncthreads();

        const __half* st = smp + (kt & 1) * STAGE_HALFS;
#pragma unroll
        for (int ks = 0; ks < BK; ks += 16) {
            // ---- load all fragments once ----
            uint32_t ah[4][4], bh[2][4];
#pragma unroll
            for (int mi = 0; mi < 4; mi++)
                ldm4(ah[mi], st + (a_row + mi * 16) * LDS + a_col + ks);
#pragma unroll
            for (int p = 0; p < 2; p++)
                ldm4(bh[p], st + ARR + (b_row + p * 16) * LDS + b_col + ks);

            uint32_t bl[2][4];
            if (C >= 2) {
#pragma unroll
                for (int p = 0; p < 2; p++)
                    ldm4(bl[p], st + 2 * ARR + (b_row + p * 16) * LDS + b_col + ks);
            }
            uint32_t al[4][4];
            if (C >= 3) {
#pragma unroll
                for (int mi = 0; mi < 4; mi++)
                    ldm4(al[mi], st + 3 * ARR + (a_row + mi * 16) * LDS + a_col + ks);
            }

            // ---- combos from registers ----
#pragma unroll
            for (int mi = 0; mi < 4; mi++)
#pragma unroll
                for (int nj = 0; nj < 4; nj++)
                    mma16816(acc[mi][nj], ah[mi], &bh[nj >> 1][(nj & 1) * 2]);
            if (C >= 2) {
#pragma unroll
                for (int mi = 0; mi < 4; mi++)
#pragma unroll
                    for (int nj = 0; nj < 4; nj++)
                        mma16816(acc[mi][nj], ah[mi], &bl[nj >> 1][(nj & 1) * 2]);
            }
            if (C >= 3) {
#pragma unroll
                for (int mi = 0; mi < 4; mi++)
#pragma unroll
                    for (int nj = 0; nj < 4; nj++)
                        mma16816(acc[mi][nj], al[mi], &bh[nj >> 1][(nj & 1) * 2]);
            }
        }
        __syncthreads();
    }

    // -------- epilogue --------
    int row0 = m0 + wm * 64 + (lane >> 2);
    int col0 = n0 + wn * 32 + (lane & 3) * 2;

    if (mode == 0) {
        float* Cp = Cf + (size_t)z * sCz;
#pragma unroll
        for (int mi = 0; mi < 4; mi++) {
#pragma unroll
            for (int nj = 0; nj < 4; nj++) {
                int r = row0 + mi * 16, c = col0 + nj * 8;
                float2 v0 = make_float2(acc[mi][nj][0], acc[mi][nj][1]);
                float2 v1 = make_float2(acc[mi][nj][2], acc[mi][nj][3]);
                *reinterpret_cast<float2*>(Cp + (size_t)r * N + c) = v0;
                *reinterpret_cast<float2*>(Cp + (size_t)(r + 8) * N + c) = v1;
            }
        }
    } else if (mode == 1) {
#pragma unroll
        for (int mi = 0; mi < 4; mi++) {
#pragma unroll
            for (int nj = 0; nj < 4; nj++) {
                int r = row0 + mi * 16, c = col0 + nj * 8;
                float b0 = bias[c], b1 = bias[c + 1];
                store_split(Chi, Clo, (size_t)r * N + c,           acc[mi][nj][0] + b0);
                store_split(Chi, Clo, (size_t)r * N + c + 1,       acc[mi][nj][1] + b1);
                store_split(Chi, Clo, (size_t)(r + 8) * N + c,     acc[mi][nj][2] + b0);
                store_split(Chi, Clo, (size_t)(r + 8) * N + c + 1, acc[mi][nj][3] + b1);
            }
        }
    } else {  // mode 2: transposed per-batch [b][n][s]
#pragma unroll
        for (int mi = 0; mi < 4; mi++) {
#pragma unroll
            for (int nj = 0; nj < 4; nj++) {
                int r = row0 + mi * 16, c = col0 + nj * 8;
                float b0 = bias[c], b1 = bias[c + 1];
#pragma unroll
                for (int rr = 0; rr < 2; rr++) {
                    int tok = r + rr * 8;
                    int bb = tok >> 12, s = tok & (S_ - 1);
                    size_t base = ((size_t)bb * E_) * S_ + s;
                    store_split(Chi, Clo, base + (size_t)c * S_,       acc[mi][nj][rr * 2 + 0] + b0);
                    store_split(Chi, Clo, base + (size_t)(c + 1) * S_, acc[mi][nj][rr * 2 + 1] + b1);
                }
            }
        }
    }
}

// ---------------- row softmax: scores fp32 -> P hi fp16 ----------------
__device__ __forceinline__ float warpMax(float v) {
#pragma unroll
    for (int o = 16; o; o >>= 1) v = fmaxf(v, __shfl_xor_sync(0xffffffffu, v, o));
    return v;
}
__device__ __forceinline__ float warpSum(float v) {
#pragma unroll
    for (int o = 16; o; o >>= 1) v += __shfl_xor_sync(0xffffffffu, v, o);
    return v;
}

__global__ void __launch_bounds__(256) softmax_kernel(const float* __restrict__ Sc,
                                                      __half* __restrict__ Ph) {
    __shared__ float red[8];
    __shared__ float bcast;
    int row = blockIdx.x;
    int t = threadIdx.x;
    int lane = t & 31, w = t >> 5;
    const float* sr = Sc + (size_t)row * S_;

    float v[16];
#pragma unroll
    for (int i = 0; i < 16; i++) v[i] = sr[i * 256 + t];

    float m = v[0];
#pragma unroll
    for (int i = 1; i < 16; i++) m = fmaxf(m, v[i]);
    m = warpMax(m);
    if (lane == 0) red[w] = m;
    __syncthreads();
    if (t == 0) {
        float x = red[0];
#pragma unroll
        for (int j = 1; j < 8; j++) x = fmaxf(x, red[j]);
        bcast = x;
    }
    __syncthreads();
    m = bcast;

    float e[16];
    float s = 0.f;
#pragma unroll
    for (int i = 0; i < 16; i++) { e[i] = __expf(v[i] - m); s += e[i]; }
    s = warpSum(s);
    __syncthreads();
    if (lane == 0) red[w] = s;
    __syncthreads();
    if (t == 0) {
        float x = 0.f;
#pragma unroll
        for (int j = 0; j < 8; j++) x += red[j];
        bcast = x;
    }
    __syncthreads();
    float inv = 1.0f / bcast;

    size_t base = (size_t)row * S_ + t;
#pragma unroll
    for (int i = 0; i < 16; i++)
        Ph[base + (size_t)i * 256] = __float2half_rn(e[i] * inv);
}

// ---------------- host ----------------
#define GETSYM(p, s) do { void* _t = nullptr; cudaGetSymbolAddress(&_t, s); p = (__half*)_t; } while (0)

extern "C" void kernel_launch(void* const* d_in, const int* in_sizes, int n_in,
                              void* d_out, int out_size) {
    const float* q_in = (const float*)d_in[0];
    const float* k_in = (const float*)d_in[1];
    const float* v_in = (const float*)d_in[2];
    const float* Wq   = (const float*)d_in[3];
    const float* bq   = (const float*)d_in[4];
    const float* Wk   = (const float*)d_in[5];
    const float* bk   = (const float*)d_in[6];
    const float* Wv   = (const float*)d_in[7];
    const float* bv   = (const float*)d_in[8];
    float* out = (float*)d_out;

    const int SMEM3 = 2 * 4 * ARR * (int)sizeof(__half);   // 81920
    const int SMEM2 = 2 * 3 * ARR * (int)sizeof(__half);   // 61440
    cudaFuncSetAttribute(gemm_split_kernel<3>, cudaFuncAttributeMaxDynamicSharedMemorySize, SMEM3);
    cudaFuncSetAttribute(gemm_split_kernel<2>, cudaFuncAttributeMaxDynamicSharedMemorySize, SMEM2);

    __half *xqh, *xql, *xkh, *xkl, *xvh, *xvl;
    __half *wqh, *wql, *wkh, *wkl, *wvh, *wvl;
    __half *qh, *ql, *kh, *kl, *vth, *vtl, *ph;
    float* sc;
    GETSYM(xqh, g_xqh); GETSYM(xql, g_xql);
    GETSYM(xkh, g_xkh); GETSYM(xkl, g_xkl);
    GETSYM(xvh, g_xvh); GETSYM(xvl, g_xvl);
    GETSYM(wqh, g_wqh); GETSYM(wql, g_wql);
    GETSYM(wkh, g_wkh); GETSYM(wkl, g_wkl);
    GETSYM(wvh, g_wvh); GETSYM(wvl, g_wvl);
    GETSYM(qh, g_qh);   GETSYM(ql, g_ql);
    GETSYM(kh, g_kh);   GETSYM(kl, g_kl);
    GETSYM(vth, g_vth); GETSYM(vtl, g_vtl);
    GETSYM(ph, g_ph);
    { void* _t = nullptr; cudaGetSymbolAddress(&_t, g_sc); sc = (float*)_t; }

    // [1][2] split inputs and weights to fp16 hi/lo
    int nx = B_ * S_ * E_;
    split3_kernel<<<(nx + 255) / 256, 256>>>(q_in, k_in, v_in, xqh, xql, xkh, xkl, xvh, xvl, nx);
    int nw = E_ * E_;
    split3_kernel<<<(nw + 255) / 256, 256>>>(Wq, Wk, Wv, wqh, wql, wkh, wkl, wvh, wvl, nw);

    // [3][4][5] QKV projections: C[16384,512] = X * W^T + b   (3-combo)
    dim3 gp(E_ / BN, (B_ * S_) / BM, 1);
    gemm_split_kernel<3><<<gp, NTHREADS, SMEM3>>>(xqh, xql, 0, wqh, wql, 0,
        B_ * S_, E_, E_, nullptr, 0, qh, ql, bq, 1);
    gemm_split_kernel<3><<<gp, NTHREADS, SMEM3>>>(xkh, xkl, 0, wkh, wkl, 0,
        B_ * S_, E_, E_, nullptr, 0, kh, kl, bk, 1);
    gemm_split_kernel<3><<<gp, NTHREADS, SMEM3>>>(xvh, xvl, 0, wvh, wvl, 0,
        B_ * S_, E_, E_, nullptr, 0, vth, vtl, bv, 2);   // V^T hi/lo [B][E][S]

    // [6] scores[b] = Q[b] * K[b]^T  (3-combo, fp32 out)  <- ncu -s 5 profiles this
    dim3 gs(S_ / BN, S_ / BM, B_);
    gemm_split_kernel<3><<<gs, NTHREADS, SMEM3>>>(qh, ql, (long long)S_ * E_,
        kh, kl, (long long)S_ * E_, S_, S_, E_,
        sc, (long long)S_ * S_, nullptr, nullptr, nullptr, 0);

    // [7] row softmax -> P hi only
    softmax_kernel<<<B_ * S_, 256>>>(sc, ph);

    // [8] O[b] = Ph[b] * (Vh+Vl)[b]  (2-combo: A hi x full B), fp32 out
    dim3 gv(E_ / BN, S_ / BM, B_);
    gemm_split_kernel<2><<<gv, NTHREADS, SMEM2>>>(ph, nullptr, (long long)S_ * S_,
        vth, vtl, (long long)E_ * S_, S_, E_, S_,
        out, (long long)S_ * E_, nullptr, nullptr, nullptr, 0);
}

// round 7
// speedup vs baseline: 1.6352x; 1.2935x over previous
#include <cuda_runtime.h>
#include <cuda_fp16.h>
#include <cstdint>

#define B_ 4
#define S_ 4096
#define E_ 512

// ---------------- GEMM tiling ----------------
#define BM 128
#define BN 128
#define BK 32
#define NTHREADS 256
#define LDS 40                    // smem row stride in halfs (pad 32->40: conflict-free ldmatrix)
#define ARR (BM * LDS)            // halfs per operand tile (5120)

// ---------------- device-global scratch (allocation-free rule) ----------------
__device__ __half g_xqh[(size_t)B_ * S_ * E_], g_xql[(size_t)B_ * S_ * E_];
__device__ __half g_xkh[(size_t)B_ * S_ * E_], g_xkl[(size_t)B_ * S_ * E_];
__device__ __half g_xvh[(size_t)B_ * S_ * E_], g_xvl[(size_t)B_ * S_ * E_];
__device__ __half g_wqh[E_ * E_], g_wql[E_ * E_];
__device__ __half g_wkh[E_ * E_], g_wkl[E_ * E_];
__device__ __half g_wvh[E_ * E_], g_wvl[E_ * E_];
__device__ __half g_qh[(size_t)B_ * S_ * E_], g_ql[(size_t)B_ * S_ * E_];
__device__ __half g_kh[(size_t)B_ * S_ * E_], g_kl[(size_t)B_ * S_ * E_];
__device__ __half g_vth[(size_t)B_ * E_ * S_];                                // V^T hi [B][E][S]
__device__ float  g_sc[(size_t)B_ * S_ * S_];                                 // scores fp32
__device__ __half g_ph[(size_t)B_ * S_ * S_];                                 // softmax probs hi

// ---------------- PTX helpers ----------------
__device__ __forceinline__ void cpasync16(const __half* smem_ptr, const __half* gptr) {
    uint32_t s = (uint32_t)__cvta_generic_to_shared((void*)smem_ptr);
    asm volatile("cp.async.cg.shared.global [%0], [%1], 16;\n" :: "r"(s), "l"(gptr));
}

__device__ __forceinline__ void ldm4(uint32_t* d, const __half* p) {
    uint32_t s = (uint32_t)__cvta_generic_to_shared((void*)p);
    asm volatile("ldmatrix.sync.aligned.m8n8.x4.shared.b16 {%0,%1,%2,%3}, [%4];"
                 : "=r"(d[0]), "=r"(d[1]), "=r"(d[2]), "=r"(d[3]) : "r"(s));
}

__device__ __forceinline__ void mma16816(float* c, const uint32_t* a, const uint32_t* b) {
    asm volatile("mma.sync.aligned.m16n8k16.row.col.f32.f16.f16.f32 "
                 "{%0,%1,%2,%3},{%4,%5,%6,%7},{%8,%9},{%0,%1,%2,%3};"
                 : "+f"(c[0]), "+f"(c[1]), "+f"(c[2]), "+f"(c[3])
                 : "r"(a[0]), "r"(a[1]), "r"(a[2]), "r"(a[3]), "r"(b[0]), "r"(b[1]));
}

__device__ __forceinline__ void store_split(__half* hi, __half* lo, size_t idx, float v) {
    __half h = __float2half_rn(v);
    hi[idx] = h;
    lo[idx] = __float2half_rn(v - __half2float(h));
}

// ---------------- split fp32 -> fp16 hi/lo (3 tensors per launch) ----------------
__global__ void split3_kernel(const float* __restrict__ a, const float* __restrict__ b,
                              const float* __restrict__ c,
                              __half* ah, __half* al, __half* bh, __half* bl,
                              __half* ch, __half* cl, int n) {
    int i = blockIdx.x * blockDim.x + threadIdx.x;
    if (i < n) {
        float v;
        __half h;
        v = a[i]; h = __float2half_rn(v); ah[i] = h; al[i] = __float2half_rn(v - __half2float(h));
        v = b[i]; h = __float2half_rn(v); bh[i] = h; bl[i] = __float2half_rn(v - __half2float(h));
        v = c[i]; h = __float2half_rn(v); ch[i] = h; cl[i] = __float2half_rn(v - __half2float(h));
    }
}

// ---------------- split-precision NT GEMM: C[M,N] = sum_k A[m,k] * B[n,k] ----------------
// K-major fp16 operands. Combos by template C:
//   C==3: Ah*Bh + Ah*Bl + Al*Bh   (full split precision)
//   C==1: Ah*Bh                   (plain fp16, fp32 accumulate)
// Stage layout: [Ah | Bh | Bl? | Al?] each ARR halfs.
// mode 0: fp32 C (+z*sCz). mode 1: (acc+bias[n]) -> hi/lo at [m*N+n].
// mode 2: (acc+bias[n]) -> hi (and lo if Clo) transposed per-batch [b][n][s].
template <int C>
__global__ void __launch_bounds__(NTHREADS)
gemm_split_kernel(const __half* __restrict__ Ah, const __half* __restrict__ Al, long long sAz,
                  const __half* __restrict__ Bh, const __half* __restrict__ Bl, long long sBz,
                  int M, int N, int K,
                  float* __restrict__ Cf, long long sCz,
                  __half* __restrict__ Chi, __half* __restrict__ Clo,
                  const float* __restrict__ bias, int mode) {
    constexpr int NTILE = (C == 3) ? 4 : 2;
    constexpr int STAGE_HALFS = NTILE * ARR;
    extern __shared__ __half smp[];
    int z = blockIdx.z;
    Ah += (size_t)z * sAz;
    Bh += (size_t)z * sBz;
    if (C >= 2) Bl += (size_t)z * sBz;
    if (C >= 3) Al += (size_t)z * sAz;

    int m0 = blockIdx.y * BM, n0 = blockIdx.x * BN;
    int t = threadIdx.x;
    int lane = t & 31, w = t >> 5;
    int wm = w & 1, wn = w >> 1;            // 2 warps along M (64 each), 4 along N (32 each)
    int quad = lane >> 3, l8 = lane & 7;

    int a_row = wm * 64 + (quad & 1) * 8 + l8;    // + mi*16
    int a_col = (quad >> 1) * 8;                  // + ks
    int b_row = wn * 32 + (quad >> 1) * 8 + l8;   // + p*16
    int b_col = (quad & 1) * 8;                   // + ks

    float acc[4][4][4];
#pragma unroll
    for (int i = 0; i < 4; i++)
#pragma unroll
        for (int j = 0; j < 4; j++)
#pragma unroll
            for (int r = 0; r < 4; r++) acc[i][j][r] = 0.f;

    auto issue_tile = [&](int k0, __half* sb) {
#pragma unroll
        for (int i = 0; i < 2; i++) {
            int id = t + i * NTHREADS;          // 0..511
            int r = id >> 2;
            int cc = (id & 3) * 8;
            size_t ga = (size_t)(m0 + r) * K + k0 + cc;
            size_t gb = (size_t)(n0 + r) * K + k0 + cc;
            int so = r * LDS + cc;
            cpasync16(sb + so, Ah + ga);
            cpasync16(sb + ARR + so, Bh + gb);
            if (C >= 3) {
                cpasync16(sb + 2 * ARR + so, Bl + gb);
                cpasync16(sb + 3 * ARR + so, Al + ga);
            }
        }
        asm volatile("cp.async.commit_group;\n" ::: "memory");
    };

    int KT = K / BK;
    issue_tile(0, smp);

    for (int kt = 0; kt < KT; kt++) {
        // one outstanding group (tile kt): wait for it
        asm volatile("cp.async.wait_group 0;\n" ::: "memory");
        // single barrier: (a) tile-kt data visible to all, (b) all warps finished
        // computing tile kt-1 (program order) -> its stage is free to overwrite
        __syncthreads();
        if (kt + 1 < KT)
            issue_tile((kt + 1) * BK, smp + ((kt + 1) & 1) * STAGE_HALFS);

        const __half* st = smp + (kt & 1) * STAGE_HALFS;
#pragma unroll
        for (int ks = 0; ks < BK; ks += 16) {
            // ---- load all fragments once ----
            uint32_t ah[4][4], bh[2][4];
#pragma unroll
            for (int mi = 0; mi < 4; mi++)
                ldm4(ah[mi], st + (a_row + mi * 16) * LDS + a_col + ks);
#pragma unroll
            for (int p = 0; p < 2; p++)
                ldm4(bh[p], st + ARR + (b_row + p * 16) * LDS + b_col + ks);

            uint32_t bl[2][4], al[4][4];
            if (C >= 3) {
#pragma unroll
                for (int p = 0; p < 2; p++)
                    ldm4(bl[p], st + 2 * ARR + (b_row + p * 16) * LDS + b_col + ks);
#pragma unroll
                for (int mi = 0; mi < 4; mi++)
                    ldm4(al[mi], st + 3 * ARR + (a_row + mi * 16) * LDS + a_col + ks);
            }

            // ---- combos from registers ----
#pragma unroll
            for (int mi = 0; mi < 4; mi++)
#pragma unroll
                for (int nj = 0; nj < 4; nj++)
                    mma16816(acc[mi][nj], ah[mi], &bh[nj >> 1][(nj & 1) * 2]);
            if (C >= 3) {
#pragma unroll
                for (int mi = 0; mi < 4; mi++)
#pragma unroll
                    for (int nj = 0; nj < 4; nj++)
                        mma16816(acc[mi][nj], ah[mi], &bl[nj >> 1][(nj & 1) * 2]);
#pragma unroll
                for (int mi = 0; mi < 4; mi++)
#pragma unroll
                    for (int nj = 0; nj < 4; nj++)
                        mma16816(acc[mi][nj], al[mi], &bh[nj >> 1][(nj & 1) * 2]);
            }
        }
    }

    // -------- epilogue --------
    int row0 = m0 + wm * 64 + (lane >> 2);
    int col0 = n0 + wn * 32 + (lane & 3) * 2;

    if (mode == 0) {
        float* Cp = Cf + (size_t)z * sCz;
#pragma unroll
        for (int mi = 0; mi < 4; mi++) {
#pragma unroll
            for (int nj = 0; nj < 4; nj++) {
                int r = row0 + mi * 16, c = col0 + nj * 8;
                float2 v0 = make_float2(acc[mi][nj][0], acc[mi][nj][1]);
                float2 v1 = make_float2(acc[mi][nj][2], acc[mi][nj][3]);
                *reinterpret_cast<float2*>(Cp + (size_t)r * N + c) = v0;
                *reinterpret_cast<float2*>(Cp + (size_t)(r + 8) * N + c) = v1;
            }
        }
    } else if (mode == 1) {
#pragma unroll
        for (int mi = 0; mi < 4; mi++) {
#pragma unroll
            for (int nj = 0; nj < 4; nj++) {
                int r = row0 + mi * 16, c = col0 + nj * 8;
                float b0 = bias[c], b1 = bias[c + 1];
#pragma unroll
                for (int rr = 0; rr < 2; rr++) {
                    float v0 = acc[mi][nj][rr * 2 + 0] + b0;
                    float v1 = acc[mi][nj][rr * 2 + 1] + b1;
                    __half h0 = __float2half_rn(v0), h1 = __float2half_rn(v1);
                    size_t idx = (size_t)(r + rr * 8) * N + c;
                    *reinterpret_cast<__half2*>(Chi + idx) = __halves2half2(h0, h1);
                    *reinterpret_cast<__half2*>(Clo + idx) = __halves2half2(
                        __float2half_rn(v0 - __half2float(h0)),
                        __float2half_rn(v1 - __half2float(h1)));
                }
            }
        }
    } else {  // mode 2: transposed per-batch [b][n][s], hi (and optional lo)
        bool wlo = (Clo != nullptr);
#pragma unroll
        for (int mi = 0; mi < 4; mi++) {
#pragma unroll
            for (int nj = 0; nj < 4; nj++) {
                int r = row0 + mi * 16, c = col0 + nj * 8;
                float b0 = bias[c], b1 = bias[c + 1];
#pragma unroll
                for (int rr = 0; rr < 2; rr++) {
                    int tok = r + rr * 8;
                    int bb = tok >> 12, s = tok & (S_ - 1);
                    size_t base = ((size_t)bb * E_) * S_ + s;
                    float v0 = acc[mi][nj][rr * 2 + 0] + b0;
                    float v1 = acc[mi][nj][rr * 2 + 1] + b1;
                    __half h0 = __float2half_rn(v0), h1 = __float2half_rn(v1);
                    Chi[base + (size_t)c * S_] = h0;
                    Chi[base + (size_t)(c + 1) * S_] = h1;
                    if (wlo) {
                        Clo[base + (size_t)c * S_] = __float2half_rn(v0 - __half2float(h0));
                        Clo[base + (size_t)(c + 1) * S_] = __float2half_rn(v1 - __half2float(h1));
                    }
                }
            }
        }
    }
}

// ---------------- row softmax: scores fp32 -> P hi fp16 ----------------
__device__ __forceinline__ float warpMax(float v) {
#pragma unroll
    for (int o = 16; o; o >>= 1) v = fmaxf(v, __shfl_xor_sync(0xffffffffu, v, o));
    return v;
}
__device__ __forceinline__ float warpSum(float v) {
#pragma unroll
    for (int o = 16; o; o >>= 1) v += __shfl_xor_sync(0xffffffffu, v, o);
    return v;
}

__global__ void __launch_bounds__(256) softmax_kernel(const float* __restrict__ Sc,
                                                      __half* __restrict__ Ph) {
    __shared__ float red[8];
    __shared__ float bcast;
    int row = blockIdx.x;
    int t = threadIdx.x;
    int lane = t & 31, w = t >> 5;
    const float* sr = Sc + (size_t)row * S_;

    float v[16];
#pragma unroll
    for (int i = 0; i < 16; i++) v[i] = sr[i * 256 + t];

    float m = v[0];
#pragma unroll
    for (int i = 1; i < 16; i++) m = fmaxf(m, v[i]);
    m = warpMax(m);
    if (lane == 0) red[w] = m;
    __syncthreads();
    if (t == 0) {
        float x = red[0];
#pragma unroll
        for (int j = 1; j < 8; j++) x = fmaxf(x, red[j]);
        bcast = x;
    }
    __syncthreads();
    m = bcast;

    float e[16];
    float s = 0.f;
#pragma unroll
    for (int i = 0; i < 16; i++) { e[i] = __expf(v[i] - m); s += e[i]; }
    s = warpSum(s);
    __syncthreads();
    if (lane == 0) red[w] = s;
    __syncthreads();
    if (t == 0) {
        float x = 0.f;
#pragma unroll
        for (int j = 0; j < 8; j++) x += red[j];
        bcast = x;
    }
    __syncthreads();
    float inv = 1.0f / bcast;

    size_t base = (size_t)row * S_ + t;
#pragma unroll
    for (int i = 0; i < 16; i++)
        Ph[base + (size_t)i * 256] = __float2half_rn(e[i] * inv);
}

// ---------------- host ----------------
#define GETSYM(p, s) do { void* _t = nullptr; cudaGetSymbolAddress(&_t, s); p = (__half*)_t; } while (0)

extern "C" void kernel_launch(void* const* d_in, const int* in_sizes, int n_in,
                              void* d_out, int out_size) {
    const float* q_in = (const float*)d_in[0];
    const float* k_in = (const float*)d_in[1];
    const float* v_in = (const float*)d_in[2];
    const float* Wq   = (const float*)d_in[3];
    const float* bq   = (const float*)d_in[4];
    const float* Wk   = (const float*)d_in[5];
    const float* bk   = (const float*)d_in[6];
    const float* Wv   = (const float*)d_in[7];
    const float* bv   = (const float*)d_in[8];
    float* out = (float*)d_out;

    const int SMEM3 = 2 * 4 * ARR * (int)sizeof(__half);   // 81920
    const int SMEM1 = 2 * 2 * ARR * (int)sizeof(__half);   // 40960
    cudaFuncSetAttribute(gemm_split_kernel<3>, cudaFuncAttributeMaxDynamicSharedMemorySize, SMEM3);
    cudaFuncSetAttribute(gemm_split_kernel<1>, cudaFuncAttributeMaxDynamicSharedMemorySize, SMEM1);

    __half *xqh, *xql, *xkh, *xkl, *xvh, *xvl;
    __half *wqh, *wql, *wkh, *wkl, *wvh, *wvl;
    __half *qh, *ql, *kh, *kl, *vth, *ph;
    float* sc;
    GETSYM(xqh, g_xqh); GETSYM(xql, g_xql);
    GETSYM(xkh, g_xkh); GETSYM(xkl, g_xkl);
    GETSYM(xvh, g_xvh); GETSYM(xvl, g_xvl);
    GETSYM(wqh, g_wqh); GETSYM(wql, g_wql);
    GETSYM(wkh, g_wkh); GETSYM(wkl, g_wkl);
    GETSYM(wvh, g_wvh); GETSYM(wvl, g_wvl);
    GETSYM(qh, g_qh);   GETSYM(ql, g_ql);
    GETSYM(kh, g_kh);   GETSYM(kl, g_kl);
    GETSYM(vth, g_vth); GETSYM(ph, g_ph);
    { void* _t = nullptr; cudaGetSymbolAddress(&_t, g_sc); sc = (float*)_t; }

    // [1][2] split inputs and weights to fp16 hi/lo
    int nx = B_ * S_ * E_;
    split3_kernel<<<(nx + 255) / 256, 256>>>(q_in, k_in, v_in, xqh, xql, xkh, xkl, xvh, xvl, nx);
    int nw = E_ * E_;
    split3_kernel<<<(nw + 255) / 256, 256>>>(Wq, Wk, Wv, wqh, wql, wkh, wkl, wvh, wvl, nw);

    // [3][4][5] QKV projections: C[16384,512] = X * W^T + b   (3-combo)
    dim3 gp(E_ / BN, (B_ * S_) / BM, 1);
    gemm_split_kernel<3><<<gp, NTHREADS, SMEM3>>>(xqh, xql, 0, wqh, wql, 0,
        B_ * S_, E_, E_, nullptr, 0, qh, ql, bq, 1);
    gemm_split_kernel<3><<<gp, NTHREADS, SMEM3>>>(xkh, xkl, 0, wkh, wkl, 0,
        B_ * S_, E_, E_, nullptr, 0, kh, kl, bk, 1);
    gemm_split_kernel<3><<<gp, NTHREADS, SMEM3>>>(xvh, xvl, 0, wvh, wvl, 0,
        B_ * S_, E_, E_, nullptr, 0, vth, nullptr, bv, 2);   // V^T hi only [B][E][S]

    // [6] scores[b] = Q[b] * K[b]^T  (3-combo, fp32 out)  <- ncu -s 5 profiles this
    dim3 gs(S_ / BN, S_ / BM, B_);
    gemm_split_kernel<3><<<gs, NTHREADS, SMEM3>>>(qh, ql, (long long)S_ * E_,
        kh, kl, (long long)S_ * E_, S_, S_, E_,
        sc, (long long)S_ * S_, nullptr, nullptr, nullptr, 0);

    // [7] row softmax -> P hi only
    softmax_kernel<<<B_ * S_, 256>>>(sc, ph);

    // [8] O[b] = Ph[b] * Vh[b]  (1-combo plain fp16), fp32 out
    dim3 gv(E_ / BN, S_ / BM, B_);
    gemm_split_kernel<1><<<gv, NTHREADS, SMEM1>>>(ph, nullptr, (long long)S_ * S_,
        vth, nullptr, (long long)E_ * S_, S_, E_, S_,
        out, (long long)S_ * E_, nullptr, nullptr, nullptr, 0);
}